// round 4
// baseline (speedup 1.0000x reference)
#include <cuda_runtime.h>
#include <math.h>

// ---------------- problem constants ----------------
#define N_GT   100000
#define N_AG   20000
#define E_GT   640000
#define E_COMM 320000
#define D_GT   32
#define D_AG   64
#define VIS    64
#define COMM   128
#define MSG    64
#define OUTD   5
#define LRELU  0.2f

// ---------------- scratch (device globals; no runtime alloc) ----------------
__device__ float g_fs1[N_GT * VIS];          // feat_gt @ w1_src
__device__ float g_fs2[N_GT * COMM];         // feat_gt @ w2_src
__device__ float g_el1[N_GT * 4];
__device__ float g_el2[N_GT * 4];
__device__ float g_hvis1[N_AG * VIS];
__device__ float g_h[N_AG * COMM];
__device__ float g_hidden[N_AG * 128];
__device__ float g_m[N_AG * MSG];
__device__ float g_xcat[N_AG * 192];         // [h | y]
__device__ float g_gi[N_AG * 384];
__device__ float g_gh[N_AG * 384];
__device__ int   g_gt_rowptr[N_AG + 1];
__device__ int   g_cm_rowptr[N_AG + 1];
__device__ int   g_gt_cursor[N_AG];
__device__ int   g_cm_cursor[N_AG];
__device__ int   g_gt_srcs[E_GT];
__device__ int   g_cm_srcs[E_COMM];
__device__ float g_wa1l[32 * 4];
__device__ float g_wa1r[64 * 4];
__device__ float g_wa2l[32 * 4];
__device__ float g_wa2r[128 * 4];

__device__ __forceinline__ float leaky(float x) { return x >= 0.f ? x : LRELU * x; }
__device__ __forceinline__ float sigmoidf(float x) { return 1.f / (1.f + __expf(-x)); }
__device__ __forceinline__ float warp_sum(float p) {
#pragma unroll
    for (int o = 16; o > 0; o >>= 1) p += __shfl_xor_sync(0xffffffffu, p, o);
    return p;
}
__device__ __forceinline__ float warp_max(float p) {
#pragma unroll
    for (int o = 16; o > 0; o >>= 1) p = fmaxf(p, __shfl_xor_sync(0xffffffffu, p, o));
    return p;
}

// ---------------- prep: fold attention vectors into weights ----------------
// wa[k][h] = sum_d W[k][h*dh+d] * a[h][d]  -> logits become GEMM columns
__global__ void k_prep(const float* __restrict__ w1s, const float* __restrict__ w1d,
                       const float* __restrict__ a1l, const float* __restrict__ a1r,
                       const float* __restrict__ w2s, const float* __restrict__ w2d,
                       const float* __restrict__ a2l, const float* __restrict__ a2r) {
    int t = threadIdx.x;  // 1024 threads
    if (t < 128) {
        int k = t >> 2, h = t & 3; float s = 0.f;
        for (int d = 0; d < 16; d++) s += w1s[k * 64 + h * 16 + d] * a1l[h * 16 + d];
        g_wa1l[k * 4 + h] = s;
    } else if (t < 384) {
        int u = t - 128; int k = u >> 2, h = u & 3; float s = 0.f;
        for (int d = 0; d < 16; d++) s += w1d[k * 64 + h * 16 + d] * a1r[h * 16 + d];
        g_wa1r[k * 4 + h] = s;
    } else if (t < 512) {
        int u = t - 384; int k = u >> 2, h = u & 3; float s = 0.f;
        for (int d = 0; d < 32; d++) s += w2s[k * 128 + h * 32 + d] * a2l[h * 32 + d];
        g_wa2l[k * 4 + h] = s;
    } else {
        int u = t - 512; int k = u >> 2, h = u & 3; float s = 0.f;
        for (int d = 0; d < 32; d++) s += w2d[k * 128 + h * 32 + d] * a2r[h * 32 + d];
        g_wa2r[k * 4 + h] = s;
    }
}

// ---------------- CSR build: zero / histogram / scan / scatter ----------------
__global__ void k_zero() {
    int i = blockIdx.x * blockDim.x + threadIdx.x;
    if (i <= N_AG) { g_gt_rowptr[i] = 0; g_cm_rowptr[i] = 0; }
    if (i < N_AG)  { g_gt_cursor[i] = 0; g_cm_cursor[i] = 0; }
}

__global__ void k_hist(const int* __restrict__ gtd, const int* __restrict__ cmd) {
    int i = blockIdx.x * blockDim.x + threadIdx.x;
    if (i < E_GT)   atomicAdd(&g_gt_rowptr[gtd[i] + 1], 1);
    if (i < E_COMM) atomicAdd(&g_cm_rowptr[cmd[i] + 1], 1);
}

__global__ void k_scan() {  // <<<2,1024>>>: block 0 = gt, block 1 = comm
    __shared__ int sm[1024];
    int* a = (blockIdx.x == 0) ? g_gt_rowptr : g_cm_rowptr;
    const int n = N_AG;      // entries 1..n inclusive-scanned; [0] stays 0
    const int PER = 20;      // 20*1024 >= 20000
    int t = threadIdx.x;
    int base = 1 + t * PER;
    int loc[PER]; int s = 0;
#pragma unroll
    for (int j = 0; j < PER; j++) {
        int idx = base + j;
        int v = (idx <= n) ? a[idx] : 0;
        s += v; loc[j] = s;
    }
    sm[t] = s; __syncthreads();
    for (int off = 1; off < 1024; off <<= 1) {
        int v = 0; if (t >= off) v = sm[t - off];
        __syncthreads(); sm[t] += v; __syncthreads();
    }
    int pre = (t > 0) ? sm[t - 1] : 0;
#pragma unroll
    for (int j = 0; j < PER; j++) {
        int idx = base + j;
        if (idx <= n) a[idx] = loc[j] + pre;
    }
}

__global__ void k_scatter(const int* __restrict__ gts, const int* __restrict__ gtd,
                          const int* __restrict__ cms, const int* __restrict__ cmd) {
    int i = blockIdx.x * blockDim.x + threadIdx.x;
    if (i < E_GT) {
        int d = gtd[i];
        int p = g_gt_rowptr[d] + atomicAdd(&g_gt_cursor[d], 1);
        g_gt_srcs[p] = gts[i];
    }
    if (i < E_COMM) {
        int d = cmd[i];
        int p = g_cm_rowptr[d] + atomicAdd(&g_cm_cursor[d], 1);
        g_cm_srcs[p] = cms[i];
    }
}

// ---------------- source-node GEMM: fs1|fs2|el1|el2 in one pass over feat_gt ----------------
__global__ void k_src(const float* __restrict__ feat,
                      const float* __restrict__ w1s, const float* __restrict__ w2s) {
    __shared__ float sf[16 * 32];
    __shared__ float sw1[32 * 64];
    __shared__ float sw2[32 * 128];
    __shared__ float sa1[32 * 4];
    __shared__ float sa2[32 * 4];
    int t = threadIdx.x;
    int r0 = blockIdx.x * 16;
    for (int i = t; i < 512; i += 256)  sf[i]  = feat[r0 * 32 + i];
    for (int i = t; i < 2048; i += 256) sw1[i] = w1s[i];
    for (int i = t; i < 4096; i += 256) sw2[i] = w2s[i];
    if (t < 128) sa1[t] = g_wa1l[t];
    else if (t < 256) sa2[t - 128] = g_wa2l[t - 128];
    __syncthreads();
    int c = t;
    if (c >= 200) return;
    const float* wp; int stride;
    if (c < 64)       { wp = sw1 + c;         stride = 64; }
    else if (c < 192) { wp = sw2 + (c - 64);  stride = 128; }
    else if (c < 196) { wp = sa1 + (c - 192); stride = 4; }
    else              { wp = sa2 + (c - 196); stride = 4; }
    float acc[16];
#pragma unroll
    for (int r = 0; r < 16; r++) acc[r] = 0.f;
    for (int k = 0; k < 32; k++) {
        float w = wp[k * stride];
#pragma unroll
        for (int r = 0; r < 16; r++) acc[r] += sf[r * 32 + k] * w;
    }
#pragma unroll
    for (int r = 0; r < 16; r++) {
        int row = r0 + r;
        if (c < 64)       g_fs1[row * 64 + c] = acc[r];
        else if (c < 192) g_fs2[row * 128 + c - 64] = acc[r];
        else if (c < 196) g_el1[row * 4 + c - 192] = acc[r];
        else              g_el2[row * 4 + c - 196] = acc[r];
    }
}

// ---------------- GAT layer 1: warp per dst node, online edge softmax ----------------
__global__ void k_gat1(const float* __restrict__ fa, const float* __restrict__ b1) {
    int gid = blockIdx.x * blockDim.x + threadIdx.x;
    int n = gid >> 5;
    int lane = threadIdx.x & 31;
    if (n >= N_AG) return;
    float fa0 = fa[n * 64 + lane], fa1 = fa[n * 64 + lane + 32];
    // er = feat_agent @ wa1r (fused)
    float er0 = warp_sum(fa0 * g_wa1r[lane * 4 + 0] + fa1 * g_wa1r[(lane + 32) * 4 + 0]);
    float er1 = warp_sum(fa0 * g_wa1r[lane * 4 + 1] + fa1 * g_wa1r[(lane + 32) * 4 + 1]);
    float er2 = warp_sum(fa0 * g_wa1r[lane * 4 + 2] + fa1 * g_wa1r[(lane + 32) * 4 + 2]);
    float er3 = warp_sum(fa0 * g_wa1r[lane * 4 + 3] + fa1 * g_wa1r[(lane + 32) * 4 + 3]);
    int beg = g_gt_rowptr[n], end = g_gt_rowptr[n + 1];
    // pass 1: per-head max
    float m0 = -1e30f, m1 = -1e30f, m2 = -1e30f, m3 = -1e30f;
    for (int i = beg + lane; i < end; i += 32) {
        int s = g_gt_srcs[i];
        float4 e = *(const float4*)(g_el1 + s * 4);
        m0 = fmaxf(m0, leaky(e.x + er0));
        m1 = fmaxf(m1, leaky(e.y + er1));
        m2 = fmaxf(m2, leaky(e.z + er2));
        m3 = fmaxf(m3, leaky(e.w + er3));
    }
    m0 = warp_max(m0); m1 = warp_max(m1); m2 = warp_max(m2); m3 = warp_max(m3);
    // pass 2: weights + weighted accumulation (lane owns dims lane, lane+32)
    float acc0 = 0.f, acc1 = 0.f, d0 = 0.f, d1 = 0.f, d2 = 0.f, d3 = 0.f;
    bool hi = (lane >= 16);
    for (int base = beg; base < end; base += 32) {
        int i = base + lane;
        int cnt = min(32, end - base);
        int s = 0; float p0 = 0.f, p1 = 0.f, p2 = 0.f, p3 = 0.f;
        if (i < end) {
            s = g_gt_srcs[i];
            float4 e = *(const float4*)(g_el1 + s * 4);
            p0 = __expf(leaky(e.x + er0) - m0);
            p1 = __expf(leaky(e.y + er1) - m1);
            p2 = __expf(leaky(e.z + er2) - m2);
            p3 = __expf(leaky(e.w + er3) - m3);
            d0 += p0; d1 += p1; d2 += p2; d3 += p3;
        }
        for (int j = 0; j < cnt; j++) {
            int sj   = __shfl_sync(0xffffffffu, s, j);
            float q0 = __shfl_sync(0xffffffffu, p0, j);
            float q1 = __shfl_sync(0xffffffffu, p1, j);
            float q2 = __shfl_sync(0xffffffffu, p2, j);
            float q3 = __shfl_sync(0xffffffffu, p3, j);
            const float* fr = g_fs1 + sj * 64;
            float wlo = hi ? q1 : q0;   // head of dim lane
            float whi = hi ? q3 : q2;   // head of dim lane+32
            acc0 += fr[lane] * wlo;
            acc1 += fr[lane + 32] * whi;
        }
    }
    d0 = warp_sum(d0); d1 = warp_sum(d1); d2 = warp_sum(d2); d3 = warp_sum(d3);
    float dlo = hi ? d1 : d0;
    float dhi = hi ? d3 : d2;
    float r0 = dlo > 0.f ? acc0 / dlo : 0.f;
    float r1 = dhi > 0.f ? acc1 / dhi : 0.f;
    r0 = fmaxf(r0 + fa0 + b1[lane], 0.f);
    r1 = fmaxf(r1 + fa1 + b1[lane + 32], 0.f);
    g_hvis1[n * 64 + lane] = r0;
    g_hvis1[n * 64 + lane + 32] = r1;
}

// ---------------- GAT layer 2 (dh=32: head of dim lane+32q is q) ----------------
__global__ void k_gat2(const float* __restrict__ fa, const float* __restrict__ b2) {
    int gid = blockIdx.x * blockDim.x + threadIdx.x;
    int n = gid >> 5;
    int lane = threadIdx.x & 31;
    if (n >= N_AG) return;
    float hv0 = g_hvis1[n * 64 + lane], hv1 = g_hvis1[n * 64 + lane + 32];
    float fa0 = fa[n * 64 + lane], fa1 = fa[n * 64 + lane + 32];
    // er2 = [hvis1 | feat_agent] @ wa2r (fused)
    float er0 = warp_sum(hv0 * g_wa2r[lane * 4 + 0] + hv1 * g_wa2r[(lane + 32) * 4 + 0] +
                         fa0 * g_wa2r[(lane + 64) * 4 + 0] + fa1 * g_wa2r[(lane + 96) * 4 + 0]);
    float er1 = warp_sum(hv0 * g_wa2r[lane * 4 + 1] + hv1 * g_wa2r[(lane + 32) * 4 + 1] +
                         fa0 * g_wa2r[(lane + 64) * 4 + 1] + fa1 * g_wa2r[(lane + 96) * 4 + 1]);
    float er2 = warp_sum(hv0 * g_wa2r[lane * 4 + 2] + hv1 * g_wa2r[(lane + 32) * 4 + 2] +
                         fa0 * g_wa2r[(lane + 64) * 4 + 2] + fa1 * g_wa2r[(lane + 96) * 4 + 2]);
    float er3 = warp_sum(hv0 * g_wa2r[lane * 4 + 3] + hv1 * g_wa2r[(lane + 32) * 4 + 3] +
                         fa0 * g_wa2r[(lane + 64) * 4 + 3] + fa1 * g_wa2r[(lane + 96) * 4 + 3]);
    int beg = g_gt_rowptr[n], end = g_gt_rowptr[n + 1];
    float m0 = -1e30f, m1 = -1e30f, m2 = -1e30f, m3 = -1e30f;
    for (int i = beg + lane; i < end; i += 32) {
        int s = g_gt_srcs[i];
        float4 e = *(const float4*)(g_el2 + s * 4);
        m0 = fmaxf(m0, leaky(e.x + er0));
        m1 = fmaxf(m1, leaky(e.y + er1));
        m2 = fmaxf(m2, leaky(e.z + er2));
        m3 = fmaxf(m3, leaky(e.w + er3));
    }
    m0 = warp_max(m0); m1 = warp_max(m1); m2 = warp_max(m2); m3 = warp_max(m3);
    float acc0 = 0.f, acc1 = 0.f, acc2 = 0.f, acc3 = 0.f;
    float d0 = 0.f, d1 = 0.f, d2 = 0.f, d3 = 0.f;
    for (int base = beg; base < end; base += 32) {
        int i = base + lane;
        int cnt = min(32, end - base);
        int s = 0; float p0 = 0.f, p1 = 0.f, p2 = 0.f, p3 = 0.f;
        if (i < end) {
            s = g_gt_srcs[i];
            float4 e = *(const float4*)(g_el2 + s * 4);
            p0 = __expf(leaky(e.x + er0) - m0);
            p1 = __expf(leaky(e.y + er1) - m1);
            p2 = __expf(leaky(e.z + er2) - m2);
            p3 = __expf(leaky(e.w + er3) - m3);
            d0 += p0; d1 += p1; d2 += p2; d3 += p3;
        }
        for (int j = 0; j < cnt; j++) {
            int sj   = __shfl_sync(0xffffffffu, s, j);
            float q0 = __shfl_sync(0xffffffffu, p0, j);
            float q1 = __shfl_sync(0xffffffffu, p1, j);
            float q2 = __shfl_sync(0xffffffffu, p2, j);
            float q3 = __shfl_sync(0xffffffffu, p3, j);
            const float* fr = g_fs2 + sj * 128;
            acc0 += fr[lane] * q0;
            acc1 += fr[lane + 32] * q1;
            acc2 += fr[lane + 64] * q2;
            acc3 += fr[lane + 96] * q3;
        }
    }
    d0 = warp_sum(d0); d1 = warp_sum(d1); d2 = warp_sum(d2); d3 = warp_sum(d3);
    float r0 = d0 > 0.f ? acc0 / d0 : 0.f;
    float r1 = d1 > 0.f ? acc1 / d1 : 0.f;
    float r2 = d2 > 0.f ? acc2 / d2 : 0.f;
    float r3 = d3 > 0.f ? acc3 / d3 : 0.f;
    r0 = fmaxf(r0 + hv0 + b2[lane], 0.f);
    r1 = fmaxf(r1 + hv1 + b2[lane + 32], 0.f);
    r2 = fmaxf(r2 + fa0 + b2[lane + 64], 0.f);
    r3 = fmaxf(r3 + fa1 + b2[lane + 96], 0.f);
    g_h[n * 128 + lane] = r0;         g_xcat[n * 192 + lane] = r0;
    g_h[n * 128 + lane + 32] = r1;    g_xcat[n * 192 + lane + 32] = r1;
    g_h[n * 128 + lane + 64] = r2;    g_xcat[n * 192 + lane + 64] = r2;
    g_h[n * 128 + lane + 96] = r3;    g_xcat[n * 192 + lane + 96] = r3;
}

// ---------------- SGEMM: 128x128 tile, BK=8, 256 thr, 8x8 micro-tile ----------------
template <int RELU>
__global__ void __launch_bounds__(256)
k_sgemm(const float* __restrict__ A, const float* __restrict__ B,
        const float* __restrict__ bias, float* __restrict__ C,
        int M, int N, int K) {
    __shared__ float As[8][128];
    __shared__ float Bs[8][128];
    int tid = threadIdx.x;
    int bm = blockIdx.y * 128, bn = blockIdx.x * 128;
    int arow = tid >> 1, ak = (tid & 1) * 4;
    int bk = tid >> 5, bc = (tid & 31) * 4;
    int tx = tid & 15, ty = tid >> 4;
    float acc[8][8];
#pragma unroll
    for (int i = 0; i < 8; i++)
#pragma unroll
        for (int j = 0; j < 8; j++) acc[i][j] = 0.f;
    for (int k0 = 0; k0 < K; k0 += 8) {
        float4 av = make_float4(0.f, 0.f, 0.f, 0.f);
        if (bm + arow < M) av = *(const float4*)(A + (bm + arow) * K + k0 + ak);
        As[ak + 0][arow] = av.x; As[ak + 1][arow] = av.y;
        As[ak + 2][arow] = av.z; As[ak + 3][arow] = av.w;
        float4 bv = make_float4(0.f, 0.f, 0.f, 0.f);
        if (bn + bc < N) bv = *(const float4*)(B + (k0 + bk) * N + bn + bc);
        *(float4*)&Bs[bk][bc] = bv;
        __syncthreads();
#pragma unroll
        for (int k = 0; k < 8; k++) {
            float af[8], bf[8];
            *(float4*)&af[0] = *(const float4*)&As[k][ty * 8];
            *(float4*)&af[4] = *(const float4*)&As[k][ty * 8 + 4];
            *(float4*)&bf[0] = *(const float4*)&Bs[k][tx * 8];
            *(float4*)&bf[4] = *(const float4*)&Bs[k][tx * 8 + 4];
#pragma unroll
            for (int i = 0; i < 8; i++)
#pragma unroll
                for (int j = 0; j < 8; j++) acc[i][j] += af[i] * bf[j];
        }
        __syncthreads();
    }
#pragma unroll
    for (int i = 0; i < 8; i++) {
        int r = bm + ty * 8 + i;
        if (r < M) {
#pragma unroll
            for (int j = 0; j < 8; j++) {
                int c = bn + tx * 8 + j;
                if (c < N) {
                    float v = acc[i][j] + bias[c];
                    if (RELU) v = fmaxf(v, 0.f);
                    C[r * N + c] = v;
                }
            }
        }
    }
}

// ---------------- comm mailbox mean: warp per node, writes y into xcat[:,128:192] ----------------
__global__ void k_yagg() {
    int gid = blockIdx.x * blockDim.x + threadIdx.x;
    int n = gid >> 5;
    int lane = threadIdx.x & 31;
    if (n >= N_AG) return;
    int beg = g_cm_rowptr[n], end = g_cm_rowptr[n + 1];
    float a0 = 0.f, a1 = 0.f;
    int i = beg;
    for (; i + 1 < end; i += 2) {
        int s0 = g_cm_srcs[i], s1 = g_cm_srcs[i + 1];
        a0 += g_m[s0 * 64 + lane] + g_m[s1 * 64 + lane];
        a1 += g_m[s0 * 64 + lane + 32] + g_m[s1 * 64 + lane + 32];
    }
    if (i < end) {
        int s = g_cm_srcs[i];
        a0 += g_m[s * 64 + lane];
        a1 += g_m[s * 64 + lane + 32];
    }
    float inv = 1.f / fmaxf((float)(end - beg), 1.f);
    g_xcat[n * 192 + 128 + lane] = a0 * inv;
    g_xcat[n * 192 + 160 + lane] = a1 * inv;
}

// ---------------- GRU elementwise ----------------
__global__ void k_gru(const float* __restrict__ hprev) {
    int idx = blockIdx.x * blockDim.x + threadIdx.x;
    if (idx >= N_AG * 128) return;
    int n = idx >> 7, c = idx & 127;
    const float* gi = g_gi + n * 384;
    const float* gh = g_gh + n * 384;
    float r  = sigmoidf(gi[c] + gh[c]);
    float zg = sigmoidf(gi[128 + c] + gh[128 + c]);
    float ng = tanhf(gi[256 + c] + r * gh[256 + c]);
    float hp = hprev[n * 128 + c];
    float hv = (1.f - zg) * ng + zg * hp;
    g_h[idx] = hv;
    g_xcat[n * 192 + c] = hv;
}

// ---------------- output: h_out = h @ out_w + out_b, plus zz = h ----------------
__global__ void k_out(const float* __restrict__ ow, const float* __restrict__ ob,
                      float* __restrict__ out, int write_zz) {
    int gid = blockIdx.x * blockDim.x + threadIdx.x;
    int n = gid >> 5;
    int lane = threadIdx.x & 31;
    if (n >= N_AG) return;
    float p[5] = {0.f, 0.f, 0.f, 0.f, 0.f};
#pragma unroll
    for (int q = 0; q < 4; q++) {
        int d = lane + 32 * q;
        float hv = g_h[n * 128 + d];
        if (write_zz) out[N_AG * OUTD + n * 128 + d] = hv;
#pragma unroll
        for (int o = 0; o < 5; o++) p[o] += hv * ow[d * 5 + o];
    }
#pragma unroll
    for (int o = 0; o < 5; o++) p[o] = warp_sum(p[o]);
    if (lane == 0) {
#pragma unroll
        for (int o = 0; o < 5; o++) out[n * 5 + o] = p[o] + ob[o];
    }
}

// ---------------- launch ----------------
extern "C" void kernel_launch(void* const* d_in, const int* in_sizes, int n_in,
                              void* d_out, int out_size) {
    const float* feat_gt    = (const float*)d_in[0];
    const float* feat_agent = (const float*)d_in[1];
    const float* z          = (const float*)d_in[2];
    const int*   gt_src     = (const int*)d_in[3];
    const int*   gt_dst     = (const int*)d_in[4];
    const int*   cm_src     = (const int*)d_in[5];
    const int*   cm_dst     = (const int*)d_in[6];
    const float* w1_src     = (const float*)d_in[7];
    const float* w1_dst     = (const float*)d_in[8];
    const float* a1_l       = (const float*)d_in[9];
    const float* a1_r       = (const float*)d_in[10];
    const float* b1         = (const float*)d_in[11];
    const float* w2_src     = (const float*)d_in[12];
    const float* w2_dst     = (const float*)d_in[13];
    const float* a2_l       = (const float*)d_in[14];
    const float* a2_r       = (const float*)d_in[15];
    const float* b2         = (const float*)d_in[16];
    const float* enc_w1     = (const float*)d_in[17];
    const float* enc_b1     = (const float*)d_in[18];
    const float* enc_w2     = (const float*)d_in[19];
    const float* enc_b2     = (const float*)d_in[20];
    const float* gru_w_ih   = (const float*)d_in[21];
    const float* gru_w_hh   = (const float*)d_in[22];
    const float* gru_b_ih   = (const float*)d_in[23];
    const float* gru_b_hh   = (const float*)d_in[24];
    const float* out_w      = (const float*)d_in[25];
    const float* out_b      = (const float*)d_in[26];
    float* out = (float*)d_out;

    float *p_h, *p_hidden, *p_m, *p_xcat, *p_gi, *p_gh;
    cudaGetSymbolAddress((void**)&p_h, g_h);
    cudaGetSymbolAddress((void**)&p_hidden, g_hidden);
    cudaGetSymbolAddress((void**)&p_m, g_m);
    cudaGetSymbolAddress((void**)&p_xcat, g_xcat);
    cudaGetSymbolAddress((void**)&p_gi, g_gi);
    cudaGetSymbolAddress((void**)&p_gh, g_gh);

    int write_zz = (out_size >= N_AG * OUTD + N_AG * COMM) ? 1 : 0;

    // graph preprocessing + GAT front-end
    k_prep<<<1, 1024>>>(w1_src, w1_dst, a1_l, a1_r, w2_src, w2_dst, a2_l, a2_r);
    k_zero<<<(N_AG + 1 + 255) / 256, 256>>>();
    k_hist<<<(E_GT + 255) / 256, 256>>>(gt_dst, cm_dst);
    k_scan<<<2, 1024>>>();
    k_scatter<<<(E_GT + 255) / 256, 256>>>(gt_src, gt_dst, cm_src, cm_dst);
    k_src<<<N_GT / 16, 256>>>(feat_gt, w1_src, w2_src);
    k_gat1<<<(N_AG * 32 + 255) / 256, 256>>>(feat_agent, b1);
    k_gat2<<<(N_AG * 32 + 255) / 256, 256>>>(feat_agent, b2);

    dim3 g128(1, (N_AG + 127) / 128);
    dim3 g384(3, (N_AG + 127) / 128);
    int gru_grid = (N_AG * 128 + 255) / 256;

    // comm step 0 (hprev = input z)
    k_sgemm<1><<<g128, 256>>>(p_h, enc_w1, enc_b1, p_hidden, N_AG, 128, 128);
    k_sgemm<1><<<g128, 256>>>(p_hidden, enc_w2, enc_b2, p_m, N_AG, 64, 128);
    k_yagg<<<(N_AG * 32 + 255) / 256, 256>>>();
    k_sgemm<0><<<g384, 256>>>(p_xcat, gru_w_ih, gru_b_ih, p_gi, N_AG, 384, 192);
    k_sgemm<0><<<g384, 256>>>(z, gru_w_hh, gru_b_hh, p_gh, N_AG, 384, 128);
    k_gru<<<gru_grid, 256>>>(z);

    // comm step 1 (hprev = zz = h from step 0)
    k_sgemm<1><<<g128, 256>>>(p_h, enc_w1, enc_b1, p_hidden, N_AG, 128, 128);
    k_sgemm<1><<<g128, 256>>>(p_hidden, enc_w2, enc_b2, p_m, N_AG, 64, 128);
    k_yagg<<<(N_AG * 32 + 255) / 256, 256>>>();
    k_sgemm<0><<<g384, 256>>>(p_xcat, gru_w_ih, gru_b_ih, p_gi, N_AG, 384, 192);
    k_sgemm<0><<<g384, 256>>>(p_h, gru_w_hh, gru_b_hh, p_gh, N_AG, 384, 128);
    k_gru<<<gru_grid, 256>>>(p_h);

    k_out<<<(N_AG * 32 + 255) / 256, 256>>>(out_w, out_b, out, write_zz);
}

// round 5
// speedup vs baseline: 1.8387x; 1.8387x over previous
#include <cuda_runtime.h>
#include <math.h>
#include <stdint.h>

// ---------------- problem constants ----------------
#define N_GT   100000
#define N_AG   20000
#define E_GT   640000
#define E_COMM 320000
#define D_GT   32
#define D_AG   64
#define VIS    64
#define COMM   128
#define MSG    64
#define OUTD   5
#define LRELU  0.2f

// ---------------- scratch (device globals; no runtime alloc) ----------------
__device__ float g_fs1[N_GT * VIS];          // feat_gt @ w1_src
__device__ float g_fs2[N_GT * COMM];         // feat_gt @ w2_src
__device__ float g_el1[N_GT * 4];
__device__ float g_el2[N_GT * 4];
__device__ float g_hvis1[N_AG * VIS];
__device__ float g_h[N_AG * COMM];
__device__ float g_hidden[N_AG * 128];
__device__ float g_m[N_AG * MSG];
__device__ float g_xcat[N_AG * 192];         // [h | y]
__device__ float g_gi[N_AG * 384];
__device__ float g_gh[N_AG * 384];
__device__ int   g_gt_rowptr[N_AG + 1];
__device__ int   g_cm_rowptr[N_AG + 1];
__device__ int   g_gt_cursor[N_AG];
__device__ int   g_cm_cursor[N_AG];
__device__ int   g_gt_srcs[E_GT];
__device__ int   g_cm_srcs[E_COMM];
__device__ float g_wa1l[32 * 4];
__device__ float g_wa1r[64 * 4];
__device__ float g_wa2l[32 * 4];
__device__ float g_wa2r[128 * 4];

__device__ __forceinline__ float leaky(float x) { return x >= 0.f ? x : LRELU * x; }
__device__ __forceinline__ float sigmoidf(float x) { return 1.f / (1.f + __expf(-x)); }
__device__ __forceinline__ float warp_sum(float p) {
#pragma unroll
    for (int o = 16; o > 0; o >>= 1) p += __shfl_xor_sync(0xffffffffu, p, o);
    return p;
}
__device__ __forceinline__ float warp_max(float p) {
#pragma unroll
    for (int o = 16; o > 0; o >>= 1) p = fmaxf(p, __shfl_xor_sync(0xffffffffu, p, o));
    return p;
}
__device__ __forceinline__ uint32_t f2tf32(float x) {
    uint32_t r;
    asm("cvt.rna.tf32.f32 %0, %1;" : "=r"(r) : "f"(x));
    return r;
}
__device__ __forceinline__ void mma_tf32(float* c, const uint32_t* a, uint32_t b0, uint32_t b1) {
    asm volatile(
        "mma.sync.aligned.m16n8k8.row.col.f32.tf32.tf32.f32 "
        "{%0,%1,%2,%3},{%4,%5,%6,%7},{%8,%9},{%0,%1,%2,%3};"
        : "+f"(c[0]), "+f"(c[1]), "+f"(c[2]), "+f"(c[3])
        : "r"(a[0]), "r"(a[1]), "r"(a[2]), "r"(a[3]), "r"(b0), "r"(b1));
}

// ---------------- prep: fold attention vectors into weights ----------------
__global__ void k_prep(const float* __restrict__ w1s, const float* __restrict__ w1d,
                       const float* __restrict__ a1l, const float* __restrict__ a1r,
                       const float* __restrict__ w2s, const float* __restrict__ w2d,
                       const float* __restrict__ a2l, const float* __restrict__ a2r) {
    int t = threadIdx.x;  // 1024 threads
    if (t < 128) {
        int k = t >> 2, h = t & 3; float s = 0.f;
        for (int d = 0; d < 16; d++) s += w1s[k * 64 + h * 16 + d] * a1l[h * 16 + d];
        g_wa1l[k * 4 + h] = s;
    } else if (t < 384) {
        int u = t - 128; int k = u >> 2, h = u & 3; float s = 0.f;
        for (int d = 0; d < 16; d++) s += w1d[k * 64 + h * 16 + d] * a1r[h * 16 + d];
        g_wa1r[k * 4 + h] = s;
    } else if (t < 512) {
        int u = t - 384; int k = u >> 2, h = u & 3; float s = 0.f;
        for (int d = 0; d < 32; d++) s += w2s[k * 128 + h * 32 + d] * a2l[h * 32 + d];
        g_wa2l[k * 4 + h] = s;
    } else {
        int u = t - 512; int k = u >> 2, h = u & 3; float s = 0.f;
        for (int d = 0; d < 32; d++) s += w2d[k * 128 + h * 32 + d] * a2r[h * 32 + d];
        g_wa2r[k * 4 + h] = s;
    }
}

// ---------------- CSR build: zero / histogram / scan / scatter ----------------
__global__ void k_zero() {
    int i = blockIdx.x * blockDim.x + threadIdx.x;
    if (i <= N_AG) { g_gt_rowptr[i] = 0; g_cm_rowptr[i] = 0; }
    if (i < N_AG)  { g_gt_cursor[i] = 0; g_cm_cursor[i] = 0; }
}

__global__ void k_hist(const int* __restrict__ gtd, const int* __restrict__ cmd) {
    int i = blockIdx.x * blockDim.x + threadIdx.x;
    if (i < E_GT)   atomicAdd(&g_gt_rowptr[gtd[i] + 1], 1);
    if (i < E_COMM) atomicAdd(&g_cm_rowptr[cmd[i] + 1], 1);
}

__global__ void k_scan() {  // <<<2,1024>>>: block 0 = gt, block 1 = comm
    __shared__ int sm[1024];
    int* a = (blockIdx.x == 0) ? g_gt_rowptr : g_cm_rowptr;
    const int n = N_AG;
    const int PER = 20;
    int t = threadIdx.x;
    int base = 1 + t * PER;
    int loc[PER]; int s = 0;
#pragma unroll
    for (int j = 0; j < PER; j++) {
        int idx = base + j;
        int v = (idx <= n) ? a[idx] : 0;
        s += v; loc[j] = s;
    }
    sm[t] = s; __syncthreads();
    for (int off = 1; off < 1024; off <<= 1) {
        int v = 0; if (t >= off) v = sm[t - off];
        __syncthreads(); sm[t] += v; __syncthreads();
    }
    int pre = (t > 0) ? sm[t - 1] : 0;
#pragma unroll
    for (int j = 0; j < PER; j++) {
        int idx = base + j;
        if (idx <= n) a[idx] = loc[j] + pre;
    }
}

__global__ void k_scatter(const int* __restrict__ gts, const int* __restrict__ gtd,
                          const int* __restrict__ cms, const int* __restrict__ cmd) {
    int i = blockIdx.x * blockDim.x + threadIdx.x;
    if (i < E_GT) {
        int d = gtd[i];
        int p = g_gt_rowptr[d] + atomicAdd(&g_gt_cursor[d], 1);
        g_gt_srcs[p] = gts[i];
    }
    if (i < E_COMM) {
        int d = cmd[i];
        int p = g_cm_rowptr[d] + atomicAdd(&g_cm_cursor[d], 1);
        g_cm_srcs[p] = cms[i];
    }
}

// ---------------- source-node GEMM: fs1|fs2|el1|el2 in one pass over feat_gt ----------------
__global__ void k_src(const float* __restrict__ feat,
                      const float* __restrict__ w1s, const float* __restrict__ w2s) {
    __shared__ float sf[16 * 32];
    __shared__ float sw1[32 * 64];
    __shared__ float sw2[32 * 128];
    __shared__ float sa1[32 * 4];
    __shared__ float sa2[32 * 4];
    int t = threadIdx.x;
    int r0 = blockIdx.x * 16;
    for (int i = t; i < 512; i += 256)  sf[i]  = feat[r0 * 32 + i];
    for (int i = t; i < 2048; i += 256) sw1[i] = w1s[i];
    for (int i = t; i < 4096; i += 256) sw2[i] = w2s[i];
    if (t < 128) sa1[t] = g_wa1l[t];
    else if (t < 256) sa2[t - 128] = g_wa2l[t - 128];
    __syncthreads();
    int c = t;
    if (c >= 200) return;
    const float* wp; int stride;
    if (c < 64)       { wp = sw1 + c;         stride = 64; }
    else if (c < 192) { wp = sw2 + (c - 64);  stride = 128; }
    else if (c < 196) { wp = sa1 + (c - 192); stride = 4; }
    else              { wp = sa2 + (c - 196); stride = 4; }
    float acc[16];
#pragma unroll
    for (int r = 0; r < 16; r++) acc[r] = 0.f;
    for (int k = 0; k < 32; k++) {
        float w = wp[k * stride];
#pragma unroll
        for (int r = 0; r < 16; r++) acc[r] += sf[r * 32 + k] * w;
    }
#pragma unroll
    for (int r = 0; r < 16; r++) {
        int row = r0 + r;
        if (c < 64)       g_fs1[row * 64 + c] = acc[r];
        else if (c < 192) g_fs2[row * 128 + c - 64] = acc[r];
        else if (c < 196) g_el1[row * 4 + c - 192] = acc[r];
        else              g_el2[row * 4 + c - 196] = acc[r];
    }
}

// ---------------- GAT layer 1: warp per dst node, online edge softmax ----------------
__global__ void k_gat1(const float* __restrict__ fa, const float* __restrict__ b1) {
    int gid = blockIdx.x * blockDim.x + threadIdx.x;
    int n = gid >> 5;
    int lane = threadIdx.x & 31;
    if (n >= N_AG) return;
    float fa0 = fa[n * 64 + lane], fa1 = fa[n * 64 + lane + 32];
    float er0 = warp_sum(fa0 * g_wa1r[lane * 4 + 0] + fa1 * g_wa1r[(lane + 32) * 4 + 0]);
    float er1 = warp_sum(fa0 * g_wa1r[lane * 4 + 1] + fa1 * g_wa1r[(lane + 32) * 4 + 1]);
    float er2 = warp_sum(fa0 * g_wa1r[lane * 4 + 2] + fa1 * g_wa1r[(lane + 32) * 4 + 2]);
    float er3 = warp_sum(fa0 * g_wa1r[lane * 4 + 3] + fa1 * g_wa1r[(lane + 32) * 4 + 3]);
    int beg = g_gt_rowptr[n], end = g_gt_rowptr[n + 1];
    float m0 = -1e30f, m1 = -1e30f, m2 = -1e30f, m3 = -1e30f;
    for (int i = beg + lane; i < end; i += 32) {
        int s = g_gt_srcs[i];
        float4 e = *(const float4*)(g_el1 + s * 4);
        m0 = fmaxf(m0, leaky(e.x + er0));
        m1 = fmaxf(m1, leaky(e.y + er1));
        m2 = fmaxf(m2, leaky(e.z + er2));
        m3 = fmaxf(m3, leaky(e.w + er3));
    }
    m0 = warp_max(m0); m1 = warp_max(m1); m2 = warp_max(m2); m3 = warp_max(m3);
    float acc0 = 0.f, acc1 = 0.f, d0 = 0.f, d1 = 0.f, d2 = 0.f, d3 = 0.f;
    bool hi = (lane >= 16);
    for (int base = beg; base < end; base += 32) {
        int i = base + lane;
        int cnt = min(32, end - base);
        int s = 0; float p0 = 0.f, p1 = 0.f, p2 = 0.f, p3 = 0.f;
        if (i < end) {
            s = g_gt_srcs[i];
            float4 e = *(const float4*)(g_el1 + s * 4);
            p0 = __expf(leaky(e.x + er0) - m0);
            p1 = __expf(leaky(e.y + er1) - m1);
            p2 = __expf(leaky(e.z + er2) - m2);
            p3 = __expf(leaky(e.w + er3) - m3);
            d0 += p0; d1 += p1; d2 += p2; d3 += p3;
        }
        for (int j = 0; j < cnt; j++) {
            int sj   = __shfl_sync(0xffffffffu, s, j);
            float q0 = __shfl_sync(0xffffffffu, p0, j);
            float q1 = __shfl_sync(0xffffffffu, p1, j);
            float q2 = __shfl_sync(0xffffffffu, p2, j);
            float q3 = __shfl_sync(0xffffffffu, p3, j);
            const float* fr = g_fs1 + sj * 64;
            float wlo = hi ? q1 : q0;
            float whi = hi ? q3 : q2;
            acc0 += fr[lane] * wlo;
            acc1 += fr[lane + 32] * whi;
        }
    }
    d0 = warp_sum(d0); d1 = warp_sum(d1); d2 = warp_sum(d2); d3 = warp_sum(d3);
    float dlo = hi ? d1 : d0;
    float dhi = hi ? d3 : d2;
    float r0 = dlo > 0.f ? acc0 / dlo : 0.f;
    float r1 = dhi > 0.f ? acc1 / dhi : 0.f;
    r0 = fmaxf(r0 + fa0 + b1[lane], 0.f);
    r1 = fmaxf(r1 + fa1 + b1[lane + 32], 0.f);
    g_hvis1[n * 64 + lane] = r0;
    g_hvis1[n * 64 + lane + 32] = r1;
}

// ---------------- GAT layer 2 (dh=32) ----------------
__global__ void k_gat2(const float* __restrict__ fa, const float* __restrict__ b2) {
    int gid = blockIdx.x * blockDim.x + threadIdx.x;
    int n = gid >> 5;
    int lane = threadIdx.x & 31;
    if (n >= N_AG) return;
    float hv0 = g_hvis1[n * 64 + lane], hv1 = g_hvis1[n * 64 + lane + 32];
    float fa0 = fa[n * 64 + lane], fa1 = fa[n * 64 + lane + 32];
    float er0 = warp_sum(hv0 * g_wa2r[lane * 4 + 0] + hv1 * g_wa2r[(lane + 32) * 4 + 0] +
                         fa0 * g_wa2r[(lane + 64) * 4 + 0] + fa1 * g_wa2r[(lane + 96) * 4 + 0]);
    float er1 = warp_sum(hv0 * g_wa2r[lane * 4 + 1] + hv1 * g_wa2r[(lane + 32) * 4 + 1] +
                         fa0 * g_wa2r[(lane + 64) * 4 + 1] + fa1 * g_wa2r[(lane + 96) * 4 + 1]);
    float er2 = warp_sum(hv0 * g_wa2r[lane * 4 + 2] + hv1 * g_wa2r[(lane + 32) * 4 + 2] +
                         fa0 * g_wa2r[(lane + 64) * 4 + 2] + fa1 * g_wa2r[(lane + 96) * 4 + 2]);
    float er3 = warp_sum(hv0 * g_wa2r[lane * 4 + 3] + hv1 * g_wa2r[(lane + 32) * 4 + 3] +
                         fa0 * g_wa2r[(lane + 64) * 4 + 3] + fa1 * g_wa2r[(lane + 96) * 4 + 3]);
    int beg = g_gt_rowptr[n], end = g_gt_rowptr[n + 1];
    float m0 = -1e30f, m1 = -1e30f, m2 = -1e30f, m3 = -1e30f;
    for (int i = beg + lane; i < end; i += 32) {
        int s = g_gt_srcs[i];
        float4 e = *(const float4*)(g_el2 + s * 4);
        m0 = fmaxf(m0, leaky(e.x + er0));
        m1 = fmaxf(m1, leaky(e.y + er1));
        m2 = fmaxf(m2, leaky(e.z + er2));
        m3 = fmaxf(m3, leaky(e.w + er3));
    }
    m0 = warp_max(m0); m1 = warp_max(m1); m2 = warp_max(m2); m3 = warp_max(m3);
    float acc0 = 0.f, acc1 = 0.f, acc2 = 0.f, acc3 = 0.f;
    float d0 = 0.f, d1 = 0.f, d2 = 0.f, d3 = 0.f;
    for (int base = beg; base < end; base += 32) {
        int i = base + lane;
        int cnt = min(32, end - base);
        int s = 0; float p0 = 0.f, p1 = 0.f, p2 = 0.f, p3 = 0.f;
        if (i < end) {
            s = g_gt_srcs[i];
            float4 e = *(const float4*)(g_el2 + s * 4);
            p0 = __expf(leaky(e.x + er0) - m0);
            p1 = __expf(leaky(e.y + er1) - m1);
            p2 = __expf(leaky(e.z + er2) - m2);
            p3 = __expf(leaky(e.w + er3) - m3);
            d0 += p0; d1 += p1; d2 += p2; d3 += p3;
        }
        for (int j = 0; j < cnt; j++) {
            int sj   = __shfl_sync(0xffffffffu, s, j);
            float q0 = __shfl_sync(0xffffffffu, p0, j);
            float q1 = __shfl_sync(0xffffffffu, p1, j);
            float q2 = __shfl_sync(0xffffffffu, p2, j);
            float q3 = __shfl_sync(0xffffffffu, p3, j);
            const float* fr = g_fs2 + sj * 128;
            acc0 += fr[lane] * q0;
            acc1 += fr[lane + 32] * q1;
            acc2 += fr[lane + 64] * q2;
            acc3 += fr[lane + 96] * q3;
        }
    }
    d0 = warp_sum(d0); d1 = warp_sum(d1); d2 = warp_sum(d2); d3 = warp_sum(d3);
    float r0 = d0 > 0.f ? acc0 / d0 : 0.f;
    float r1 = d1 > 0.f ? acc1 / d1 : 0.f;
    float r2 = d2 > 0.f ? acc2 / d2 : 0.f;
    float r3 = d3 > 0.f ? acc3 / d3 : 0.f;
    r0 = fmaxf(r0 + hv0 + b2[lane], 0.f);
    r1 = fmaxf(r1 + hv1 + b2[lane + 32], 0.f);
    r2 = fmaxf(r2 + fa0 + b2[lane + 64], 0.f);
    r3 = fmaxf(r3 + fa1 + b2[lane + 96], 0.f);
    g_h[n * 128 + lane] = r0;         g_xcat[n * 192 + lane] = r0;
    g_h[n * 128 + lane + 32] = r1;    g_xcat[n * 192 + lane + 32] = r1;
    g_h[n * 128 + lane + 64] = r2;    g_xcat[n * 192 + lane + 64] = r2;
    g_h[n * 128 + lane + 96] = r3;    g_xcat[n * 192 + lane + 96] = r3;
}

// ---------------- TF32 tensor-core GEMM: C[M,N] = A[M,K] @ B[K,N] + bias ----------------
// BM=128, BK=32, 256 threads. BN in {64,128}. A,B row-major, ld = K / N.
// Smem: A ld=36 -> frag-load bank = 4g+t4 (conflict-free); B ld=BN+8 -> bank = 8t4+g (conflict-free).
template <int BN, int RELU>
__global__ void __launch_bounds__(256)
k_mma(const float* __restrict__ A, const float* __restrict__ B,
      const float* __restrict__ bias, float* __restrict__ C,
      int M, int N, int K) {
    constexpr int WN  = BN / 64;       // warps along N
    constexpr int WM  = 8 / WN;        // warps along M
    constexpr int WTM = 128 / WM;      // warp tile rows (32 or 16)
    constexpr int MT  = WTM / 16;      // m16 tiles per warp (2 or 1)
    constexpr int ALD = 36;
    constexpr int BLD = BN + 8;

    __shared__ uint32_t As[128 * ALD];
    __shared__ uint32_t Bs[32 * BLD];

    const int tid  = threadIdx.x;
    const int lane = tid & 31;
    const int warp = tid >> 5;
    const int g    = lane >> 2;
    const int t4   = lane & 3;
    const int wm   = warp / WN;
    const int wn   = warp % WN;
    const int wrow = wm * WTM;
    const int wcol = wn * 64;
    const int bm   = blockIdx.y * 128;
    const int bn   = blockIdx.x * BN;

    float acc[MT][8][4];
#pragma unroll
    for (int mt = 0; mt < MT; mt++)
#pragma unroll
        for (int nt = 0; nt < 8; nt++)
#pragma unroll
            for (int q = 0; q < 4; q++) acc[mt][nt][q] = 0.f;

    for (int k0 = 0; k0 < K; k0 += 32) {
        // load A tile 128x32 (tf32-convert on the way in)
#pragma unroll
        for (int it = 0; it < 4; it++) {
            int r = it * 32 + (tid >> 3);
            int c = (tid & 7) * 4;
            int gr = bm + r;
            float4 v = make_float4(0.f, 0.f, 0.f, 0.f);
            if (gr < M) v = *(const float4*)(A + (size_t)gr * K + k0 + c);
            uint4 u;
            u.x = f2tf32(v.x); u.y = f2tf32(v.y); u.z = f2tf32(v.z); u.w = f2tf32(v.w);
            *(uint4*)&As[r * ALD + c] = u;
        }
        // load B tile 32xBN
        if (BN == 128) {
#pragma unroll
            for (int it = 0; it < 4; it++) {
                int r = it * 8 + (tid >> 5);
                int c = (tid & 31) * 4;
                float4 v = *(const float4*)(B + (size_t)(k0 + r) * N + bn + c);
                uint4 u;
                u.x = f2tf32(v.x); u.y = f2tf32(v.y); u.z = f2tf32(v.z); u.w = f2tf32(v.w);
                *(uint4*)&Bs[r * BLD + c] = u;
            }
        } else {
#pragma unroll
            for (int it = 0; it < 2; it++) {
                int r = it * 16 + (tid >> 4);
                int c = (tid & 15) * 4;
                float4 v = *(const float4*)(B + (size_t)(k0 + r) * N + bn + c);
                uint4 u;
                u.x = f2tf32(v.x); u.y = f2tf32(v.y); u.z = f2tf32(v.z); u.w = f2tf32(v.w);
                *(uint4*)&Bs[r * BLD + c] = u;
            }
        }
        __syncthreads();

#pragma unroll
        for (int ks = 0; ks < 4; ks++) {
            int kk = ks * 8;
            uint32_t a[MT][4];
#pragma unroll
            for (int mt = 0; mt < MT; mt++) {
                int r = wrow + mt * 16;
                a[mt][0] = As[(r + g) * ALD + kk + t4];
                a[mt][1] = As[(r + g + 8) * ALD + kk + t4];
                a[mt][2] = As[(r + g) * ALD + kk + t4 + 4];
                a[mt][3] = As[(r + g + 8) * ALD + kk + t4 + 4];
            }
#pragma unroll
            for (int nt = 0; nt < 8; nt++) {
                int n0 = wcol + nt * 8;
                uint32_t b0 = Bs[(kk + t4) * BLD + n0 + g];
                uint32_t b1 = Bs[(kk + t4 + 4) * BLD + n0 + g];
#pragma unroll
                for (int mt = 0; mt < MT; mt++)
                    mma_tf32(acc[mt][nt], a[mt], b0, b1);
            }
        }
        __syncthreads();
    }

    // epilogue: bias (+ReLU), guarded stores
#pragma unroll
    for (int mt = 0; mt < MT; mt++) {
#pragma unroll
        for (int nt = 0; nt < 8; nt++) {
            int rr = bm + wrow + mt * 16 + g;
            int cc = bn + wcol + nt * 8 + 2 * t4;
            float bb0 = bias[cc], bb1 = bias[cc + 1];
            if (rr < M) {
                float v0 = acc[mt][nt][0] + bb0;
                float v1 = acc[mt][nt][1] + bb1;
                if (RELU) { v0 = fmaxf(v0, 0.f); v1 = fmaxf(v1, 0.f); }
                *(float2*)(C + (size_t)rr * N + cc) = make_float2(v0, v1);
            }
            if (rr + 8 < M) {
                float v0 = acc[mt][nt][2] + bb0;
                float v1 = acc[mt][nt][3] + bb1;
                if (RELU) { v0 = fmaxf(v0, 0.f); v1 = fmaxf(v1, 0.f); }
                *(float2*)(C + (size_t)(rr + 8) * N + cc) = make_float2(v0, v1);
            }
        }
    }
}

// ---------------- comm mailbox mean ----------------
__global__ void k_yagg() {
    int gid = blockIdx.x * blockDim.x + threadIdx.x;
    int n = gid >> 5;
    int lane = threadIdx.x & 31;
    if (n >= N_AG) return;
    int beg = g_cm_rowptr[n], end = g_cm_rowptr[n + 1];
    float a0 = 0.f, a1 = 0.f;
    int i = beg;
    for (; i + 1 < end; i += 2) {
        int s0 = g_cm_srcs[i], s1 = g_cm_srcs[i + 1];
        a0 += g_m[s0 * 64 + lane] + g_m[s1 * 64 + lane];
        a1 += g_m[s0 * 64 + lane + 32] + g_m[s1 * 64 + lane + 32];
    }
    if (i < end) {
        int s = g_cm_srcs[i];
        a0 += g_m[s * 64 + lane];
        a1 += g_m[s * 64 + lane + 32];
    }
    float inv = 1.f / fmaxf((float)(end - beg), 1.f);
    g_xcat[n * 192 + 128 + lane] = a0 * inv;
    g_xcat[n * 192 + 160 + lane] = a1 * inv;
}

// ---------------- GRU elementwise ----------------
__global__ void k_gru(const float* __restrict__ hprev) {
    int idx = blockIdx.x * blockDim.x + threadIdx.x;
    if (idx >= N_AG * 128) return;
    int n = idx >> 7, c = idx & 127;
    const float* gi = g_gi + n * 384;
    const float* gh = g_gh + n * 384;
    float r  = sigmoidf(gi[c] + gh[c]);
    float zg = sigmoidf(gi[128 + c] + gh[128 + c]);
    float ng = tanhf(gi[256 + c] + r * gh[256 + c]);
    float hp = hprev[n * 128 + c];
    float hv = (1.f - zg) * ng + zg * hp;
    g_h[idx] = hv;
    g_xcat[n * 192 + c] = hv;
}

// ---------------- output ----------------
__global__ void k_out(const float* __restrict__ ow, const float* __restrict__ ob,
                      float* __restrict__ out, int write_zz) {
    int gid = blockIdx.x * blockDim.x + threadIdx.x;
    int n = gid >> 5;
    int lane = threadIdx.x & 31;
    if (n >= N_AG) return;
    float p[5] = {0.f, 0.f, 0.f, 0.f, 0.f};
#pragma unroll
    for (int q = 0; q < 4; q++) {
        int d = lane + 32 * q;
        float hv = g_h[n * 128 + d];
        if (write_zz) out[N_AG * OUTD + n * 128 + d] = hv;
#pragma unroll
        for (int o = 0; o < 5; o++) p[o] += hv * ow[d * 5 + o];
    }
#pragma unroll
    for (int o = 0; o < 5; o++) p[o] = warp_sum(p[o]);
    if (lane == 0) {
#pragma unroll
        for (int o = 0; o < 5; o++) out[n * 5 + o] = p[o] + ob[o];
    }
}

// ---------------- launch ----------------
extern "C" void kernel_launch(void* const* d_in, const int* in_sizes, int n_in,
                              void* d_out, int out_size) {
    const float* feat_gt    = (const float*)d_in[0];
    const float* feat_agent = (const float*)d_in[1];
    const float* z          = (const float*)d_in[2];
    const int*   gt_src     = (const int*)d_in[3];
    const int*   gt_dst     = (const int*)d_in[4];
    const int*   cm_src     = (const int*)d_in[5];
    const int*   cm_dst     = (const int*)d_in[6];
    const float* w1_src     = (const float*)d_in[7];
    const float* w1_dst     = (const float*)d_in[8];
    const float* a1_l       = (const float*)d_in[9];
    const float* a1_r       = (const float*)d_in[10];
    const float* b1         = (const float*)d_in[11];
    const float* w2_src     = (const float*)d_in[12];
    const float* w2_dst     = (const float*)d_in[13];
    const float* a2_l       = (const float*)d_in[14];
    const float* a2_r       = (const float*)d_in[15];
    const float* b2         = (const float*)d_in[16];
    const float* enc_w1     = (const float*)d_in[17];
    const float* enc_b1     = (const float*)d_in[18];
    const float* enc_w2     = (const float*)d_in[19];
    const float* enc_b2     = (const float*)d_in[20];
    const float* gru_w_ih   = (const float*)d_in[21];
    const float* gru_w_hh   = (const float*)d_in[22];
    const float* gru_b_ih   = (const float*)d_in[23];
    const float* gru_b_hh   = (const float*)d_in[24];
    const float* out_w      = (const float*)d_in[25];
    const float* out_b      = (const float*)d_in[26];
    float* out = (float*)d_out;

    float *p_h, *p_hidden, *p_m, *p_xcat, *p_gi, *p_gh;
    cudaGetSymbolAddress((void**)&p_h, g_h);
    cudaGetSymbolAddress((void**)&p_hidden, g_hidden);
    cudaGetSymbolAddress((void**)&p_m, g_m);
    cudaGetSymbolAddress((void**)&p_xcat, g_xcat);
    cudaGetSymbolAddress((void**)&p_gi, g_gi);
    cudaGetSymbolAddress((void**)&p_gh, g_gh);

    int write_zz = (out_size >= N_AG * OUTD + N_AG * COMM) ? 1 : 0;

    // graph preprocessing + GAT front-end
    k_prep<<<1, 1024>>>(w1_src, w1_dst, a1_l, a1_r, w2_src, w2_dst, a2_l, a2_r);
    k_zero<<<(N_AG + 1 + 255) / 256, 256>>>();
    k_hist<<<(E_GT + 255) / 256, 256>>>(gt_dst, cm_dst);
    k_scan<<<2, 1024>>>();
    k_scatter<<<(E_GT + 255) / 256, 256>>>(gt_src, gt_dst, cm_src, cm_dst);
    k_src<<<N_GT / 16, 256>>>(feat_gt, w1_src, w2_src);
    k_gat1<<<(N_AG * 32 + 255) / 256, 256>>>(feat_agent, b1);
    k_gat2<<<(N_AG * 32 + 255) / 256, 256>>>(feat_agent, b2);

    const int MB = (N_AG + 127) / 128;   // 157
    dim3 ge1(1, MB), ge2(1, MB), gg(3, MB);
    int gru_grid = (N_AG * 128 + 255) / 256;

    // comm step 0 (hprev = input z)
    k_mma<128, 1><<<ge1, 256>>>(p_h, enc_w1, enc_b1, p_hidden, N_AG, 128, 128);
    k_mma<64, 1><<<ge2, 256>>>(p_hidden, enc_w2, enc_b2, p_m, N_AG, 64, 128);
    k_yagg<<<(N_AG * 32 + 255) / 256, 256>>>();
    k_mma<128, 0><<<gg, 256>>>(p_xcat, gru_w_ih, gru_b_ih, p_gi, N_AG, 384, 192);
    k_mma<128, 0><<<gg, 256>>>(z, gru_w_hh, gru_b_hh, p_gh, N_AG, 384, 128);
    k_gru<<<gru_grid, 256>>>(z);

    // comm step 1 (hprev = zz = h from step 0)
    k_mma<128, 1><<<ge1, 256>>>(p_h, enc_w1, enc_b1, p_hidden, N_AG, 128, 128);
    k_mma<64, 1><<<ge2, 256>>>(p_hidden, enc_w2, enc_b2, p_m, N_AG, 64, 128);
    k_yagg<<<(N_AG * 32 + 255) / 256, 256>>>();
    k_mma<128, 0><<<gg, 256>>>(p_xcat, gru_w_ih, gru_b_ih, p_gi, N_AG, 384, 192);
    k_mma<128, 0><<<gg, 256>>>(p_h, gru_w_hh, gru_b_hh, p_gh, N_AG, 384, 128);
    k_gru<<<gru_grid, 256>>>(p_h);

    k_out<<<(N_AG * 32 + 255) / 256, 256>>>(out_w, out_b, out, write_zz);
}

// round 6
// speedup vs baseline: 2.0479x; 1.1137x over previous
#include <cuda_runtime.h>
#include <math.h>
#include <stdint.h>

// ---------------- problem constants ----------------
#define N_GT   100000
#define N_AG   20000
#define E_GT   640000
#define E_COMM 320000
#define D_GT   32
#define D_AG   64
#define VIS    64
#define COMM   128
#define MSG    64
#define OUTD   5
#define LRELU  0.2f

// ---------------- scratch (device globals; no runtime alloc) ----------------
// fsall row layout (stride 256 floats = 1KB): [0:64) fs1, [64:192) fs2, [192:196) el1, [196:200) el2
__device__ float g_fsall[N_GT * 256];
__device__ float g_bsrc[32 * 256];           // packed B for the src projection GEMM
__device__ float g_h[N_AG * COMM];
__device__ float g_hidden[N_AG * 128];
__device__ float g_m[N_AG * MSG];
__device__ float g_xcat[N_AG * 192];         // [h | y]
__device__ float g_gi[N_AG * 384];
__device__ float g_gh[N_AG * 384];
__device__ int   g_gt_rowptr[N_AG + 1];
__device__ int   g_cm_rowptr[N_AG + 1];
__device__ int   g_gt_cursor[N_AG];
__device__ int   g_cm_cursor[N_AG];
__device__ int   g_gt_srcs[E_GT];
__device__ int   g_cm_srcs[E_COMM];
__device__ float g_wa1l[32 * 4];
__device__ float g_wa1r[64 * 4];
__device__ float g_wa2l[32 * 4];
__device__ float g_wa2r[128 * 4];

__device__ __forceinline__ float leaky(float x) { return x >= 0.f ? x : LRELU * x; }
__device__ __forceinline__ float sigmoidf(float x) { return 1.f / (1.f + __expf(-x)); }
__device__ __forceinline__ float warp_sum(float p) {
#pragma unroll
    for (int o = 16; o > 0; o >>= 1) p += __shfl_xor_sync(0xffffffffu, p, o);
    return p;
}
__device__ __forceinline__ uint32_t f2tf32(float x) {
    uint32_t r;
    asm("cvt.rna.tf32.f32 %0, %1;" : "=r"(r) : "f"(x));
    return r;
}
__device__ __forceinline__ void mma_tf32(float* c, const uint32_t* a, uint32_t b0, uint32_t b1) {
    asm volatile(
        "mma.sync.aligned.m16n8k8.row.col.f32.tf32.tf32.f32 "
        "{%0,%1,%2,%3},{%4,%5,%6,%7},{%8,%9},{%0,%1,%2,%3};"
        : "+f"(c[0]), "+f"(c[1]), "+f"(c[2]), "+f"(c[3])
        : "r"(a[0]), "r"(a[1]), "r"(a[2]), "r"(a[3]), "r"(b0), "r"(b1));
}

// ---------------- prep: fold attention vectors into weights ----------------
__global__ void k_prep(const float* __restrict__ w1s, const float* __restrict__ w1d,
                       const float* __restrict__ a1l, const float* __restrict__ a1r,
                       const float* __restrict__ w2s, const float* __restrict__ w2d,
                       const float* __restrict__ a2l, const float* __restrict__ a2r) {
    int t = threadIdx.x;  // 1024 threads
    if (t < 128) {
        int k = t >> 2, h = t & 3; float s = 0.f;
        for (int d = 0; d < 16; d++) s += w1s[k * 64 + h * 16 + d] * a1l[h * 16 + d];
        g_wa1l[k * 4 + h] = s;
    } else if (t < 384) {
        int u = t - 128; int k = u >> 2, h = u & 3; float s = 0.f;
        for (int d = 0; d < 16; d++) s += w1d[k * 64 + h * 16 + d] * a1r[h * 16 + d];
        g_wa1r[k * 4 + h] = s;
    } else if (t < 512) {
        int u = t - 384; int k = u >> 2, h = u & 3; float s = 0.f;
        for (int d = 0; d < 32; d++) s += w2s[k * 128 + h * 32 + d] * a2l[h * 32 + d];
        g_wa2l[k * 4 + h] = s;
    } else {
        int u = t - 512; int k = u >> 2, h = u & 3; float s = 0.f;
        for (int d = 0; d < 32; d++) s += w2d[k * 128 + h * 32 + d] * a2r[h * 32 + d];
        g_wa2r[k * 4 + h] = s;
    }
}

// pack B for the fused src GEMM: [32][256] = [w1s | w2s | wa1l | wa2l | 0pad]
__global__ void k_pack(const float* __restrict__ w1s, const float* __restrict__ w2s) {
    int i = blockIdx.x * blockDim.x + threadIdx.x;  // 32*256
    int k = i >> 8, c = i & 255;
    float v = 0.f;
    if (c < 64)       v = w1s[k * 64 + c];
    else if (c < 192) v = w2s[k * 128 + (c - 64)];
    else if (c < 196) v = g_wa1l[k * 4 + (c - 192)];
    else if (c < 200) v = g_wa2l[k * 4 + (c - 196)];
    g_bsrc[k * 256 + c] = v;
}

// ---------------- CSR build ----------------
__global__ void k_zero() {
    int i = blockIdx.x * blockDim.x + threadIdx.x;
    if (i <= N_AG) { g_gt_rowptr[i] = 0; g_cm_rowptr[i] = 0; }
    if (i < N_AG)  { g_gt_cursor[i] = 0; g_cm_cursor[i] = 0; }
}

__global__ void k_hist(const int* __restrict__ gtd, const int* __restrict__ cmd) {
    int i = blockIdx.x * blockDim.x + threadIdx.x;
    if (i < E_GT)   atomicAdd(&g_gt_rowptr[gtd[i] + 1], 1);
    if (i < E_COMM) atomicAdd(&g_cm_rowptr[cmd[i] + 1], 1);
}

__global__ void k_scan() {  // <<<2,1024>>>: block 0 = gt, block 1 = comm
    __shared__ int sm[1024];
    int* a = (blockIdx.x == 0) ? g_gt_rowptr : g_cm_rowptr;
    const int n = N_AG;
    const int PER = 20;
    int t = threadIdx.x;
    int base = 1 + t * PER;
    int loc[PER]; int s = 0;
#pragma unroll
    for (int j = 0; j < PER; j++) {
        int idx = base + j;
        int v = (idx <= n) ? a[idx] : 0;
        s += v; loc[j] = s;
    }
    sm[t] = s; __syncthreads();
    for (int off = 1; off < 1024; off <<= 1) {
        int v = 0; if (t >= off) v = sm[t - off];
        __syncthreads(); sm[t] += v; __syncthreads();
    }
    int pre = (t > 0) ? sm[t - 1] : 0;
#pragma unroll
    for (int j = 0; j < PER; j++) {
        int idx = base + j;
        if (idx <= n) a[idx] = loc[j] + pre;
    }
}

__global__ void k_scatter(const int* __restrict__ gts, const int* __restrict__ gtd,
                          const int* __restrict__ cms, const int* __restrict__ cmd) {
    int i = blockIdx.x * blockDim.x + threadIdx.x;
    if (i < E_GT) {
        int d = gtd[i];
        int p = g_gt_rowptr[d] + atomicAdd(&g_gt_cursor[d], 1);
        g_gt_srcs[p] = gts[i];
    }
    if (i < E_COMM) {
        int d = cmd[i];
        int p = g_cm_rowptr[d] + atomicAdd(&g_cm_cursor[d], 1);
        g_cm_srcs[p] = cms[i];
    }
}

// ---------------- src projection GEMM (split-tf32, fp32-class accuracy) ----------------
// C[100000, 200] = feat[100000,32] @ g_bsrc[32,256(200)], stored stride 256.
// BM=64, BN=64, 256 thr (8 warps as 4x2), K=32 single slab. 3-MMA split: hh + hl + lh.
__global__ void __launch_bounds__(256) k_srcmma(const float* __restrict__ feat) {
    constexpr int ALD = 36, BLD = 72;
    __shared__ uint32_t Ah[64 * ALD], Al[64 * ALD];
    __shared__ uint32_t Bh[32 * BLD], Bl[32 * BLD];
    int tid = threadIdx.x, lane = tid & 31, warp = tid >> 5;
    int g = lane >> 2, t4 = lane & 3;
    int wrow = (warp >> 1) * 16, wcol = (warp & 1) * 32;
    int bm = blockIdx.y * 64, bn = blockIdx.x * 64;

    float acc[4][4];
#pragma unroll
    for (int nt = 0; nt < 4; nt++)
#pragma unroll
        for (int q = 0; q < 4; q++) acc[nt][q] = 0.f;

    // load A 64x32
#pragma unroll
    for (int it = 0; it < 2; it++) {
        int r = it * 32 + (tid >> 3);
        int c = (tid & 7) * 4;
        int gr = bm + r;
        float4 v = make_float4(0.f, 0.f, 0.f, 0.f);
        if (gr < N_GT) v = *(const float4*)(feat + (size_t)gr * 32 + c);
        uint32_t hx = f2tf32(v.x), hy = f2tf32(v.y), hz = f2tf32(v.z), hw = f2tf32(v.w);
        uint4 uh = make_uint4(hx, hy, hz, hw);
        uint4 ul = make_uint4(f2tf32(v.x - __uint_as_float(hx)),
                              f2tf32(v.y - __uint_as_float(hy)),
                              f2tf32(v.z - __uint_as_float(hz)),
                              f2tf32(v.w - __uint_as_float(hw)));
        *(uint4*)&Ah[r * ALD + c] = uh;
        *(uint4*)&Al[r * ALD + c] = ul;
    }
    // load B 32x64 from packed g_bsrc (row stride 256)
#pragma unroll
    for (int it = 0; it < 2; it++) {
        int r = it * 16 + (tid >> 4);
        int c = (tid & 15) * 4;
        float4 v = *(const float4*)(g_bsrc + r * 256 + bn + c);
        uint32_t hx = f2tf32(v.x), hy = f2tf32(v.y), hz = f2tf32(v.z), hw = f2tf32(v.w);
        uint4 uh = make_uint4(hx, hy, hz, hw);
        uint4 ul = make_uint4(f2tf32(v.x - __uint_as_float(hx)),
                              f2tf32(v.y - __uint_as_float(hy)),
                              f2tf32(v.z - __uint_as_float(hz)),
                              f2tf32(v.w - __uint_as_float(hw)));
        *(uint4*)&Bh[r * BLD + c] = uh;
        *(uint4*)&Bl[r * BLD + c] = ul;
    }
    __syncthreads();

#pragma unroll
    for (int ks = 0; ks < 4; ks++) {
        int kk = ks * 8;
        uint32_t ah[4], al[4];
        ah[0] = Ah[(wrow + g) * ALD + kk + t4];
        ah[1] = Ah[(wrow + g + 8) * ALD + kk + t4];
        ah[2] = Ah[(wrow + g) * ALD + kk + t4 + 4];
        ah[3] = Ah[(wrow + g + 8) * ALD + kk + t4 + 4];
        al[0] = Al[(wrow + g) * ALD + kk + t4];
        al[1] = Al[(wrow + g + 8) * ALD + kk + t4];
        al[2] = Al[(wrow + g) * ALD + kk + t4 + 4];
        al[3] = Al[(wrow + g + 8) * ALD + kk + t4 + 4];
#pragma unroll
        for (int nt = 0; nt < 4; nt++) {
            int n0 = wcol + nt * 8;
            uint32_t bh0 = Bh[(kk + t4) * BLD + n0 + g];
            uint32_t bh1 = Bh[(kk + t4 + 4) * BLD + n0 + g];
            uint32_t bl0 = Bl[(kk + t4) * BLD + n0 + g];
            uint32_t bl1 = Bl[(kk + t4 + 4) * BLD + n0 + g];
            mma_tf32(acc[nt], ah, bh0, bh1);
            mma_tf32(acc[nt], ah, bl0, bl1);
            mma_tf32(acc[nt], al, bh0, bh1);
        }
    }

#pragma unroll
    for (int nt = 0; nt < 4; nt++) {
        int rr = bm + wrow + g;
        int cc = bn + wcol + nt * 8 + 2 * t4;
        if (cc < 200) {
            if (rr < N_GT)
                *(float2*)(g_fsall + (size_t)rr * 256 + cc) = make_float2(acc[nt][0], acc[nt][1]);
            if (rr + 8 < N_GT)
                *(float2*)(g_fsall + (size_t)(rr + 8) * 256 + cc) = make_float2(acc[nt][2], acc[nt][3]);
        }
    }
}

// ---------------- merged GAT: both layers, one edge pass each, hvis1 in regs ----------------
__global__ void k_gat(const float* __restrict__ fa_, const float* __restrict__ b1,
                      const float* __restrict__ b2) {
    int gid = blockIdx.x * blockDim.x + threadIdx.x;
    int n = gid >> 5;
    int lane = threadIdx.x & 31;
    if (n >= N_AG) return;
    float fa0 = fa_[n * 64 + lane], fa1 = fa_[n * 64 + lane + 32];
    bool hi = (lane >= 16);
    int beg = g_gt_rowptr[n], end = g_gt_rowptr[n + 1];

    // ---- layer 1 ----
    float er0 = warp_sum(fa0 * g_wa1r[lane * 4 + 0] + fa1 * g_wa1r[(lane + 32) * 4 + 0]);
    float er1 = warp_sum(fa0 * g_wa1r[lane * 4 + 1] + fa1 * g_wa1r[(lane + 32) * 4 + 1]);
    float er2 = warp_sum(fa0 * g_wa1r[lane * 4 + 2] + fa1 * g_wa1r[(lane + 32) * 4 + 2]);
    float er3 = warp_sum(fa0 * g_wa1r[lane * 4 + 3] + fa1 * g_wa1r[(lane + 32) * 4 + 3]);
    float acc0 = 0.f, acc1 = 0.f, d0 = 0.f, d1 = 0.f, d2 = 0.f, d3 = 0.f;
    for (int base = beg; base < end; base += 32) {
        int i = base + lane;
        int cnt = min(32, end - base);
        int s = 0; float p0 = 0.f, p1 = 0.f, p2 = 0.f, p3 = 0.f;
        if (i < end) {
            s = g_gt_srcs[i];
            float4 e = *(const float4*)(g_fsall + (size_t)s * 256 + 192);
            p0 = __expf(leaky(e.x + er0));
            p1 = __expf(leaky(e.y + er1));
            p2 = __expf(leaky(e.z + er2));
            p3 = __expf(leaky(e.w + er3));
            d0 += p0; d1 += p1; d2 += p2; d3 += p3;
        }
        for (int j = 0; j < cnt; j++) {
            int sj   = __shfl_sync(0xffffffffu, s, j);
            float q0 = __shfl_sync(0xffffffffu, p0, j);
            float q1 = __shfl_sync(0xffffffffu, p1, j);
            float q2 = __shfl_sync(0xffffffffu, p2, j);
            float q3 = __shfl_sync(0xffffffffu, p3, j);
            const float* fr = g_fsall + (size_t)sj * 256;
            acc0 += fr[lane] * (hi ? q1 : q0);
            acc1 += fr[lane + 32] * (hi ? q3 : q2);
        }
    }
    d0 = warp_sum(d0); d1 = warp_sum(d1); d2 = warp_sum(d2); d3 = warp_sum(d3);
    float dlo = hi ? d1 : d0;
    float dhi = hi ? d3 : d2;
    float hv0 = fmaxf((dlo > 0.f ? acc0 / dlo : 0.f) + fa0 + b1[lane], 0.f);
    float hv1 = fmaxf((dhi > 0.f ? acc1 / dhi : 0.f) + fa1 + b1[lane + 32], 0.f);

    // ---- layer 2 ----
    float f0 = warp_sum(hv0 * g_wa2r[lane * 4 + 0] + hv1 * g_wa2r[(lane + 32) * 4 + 0] +
                        fa0 * g_wa2r[(lane + 64) * 4 + 0] + fa1 * g_wa2r[(lane + 96) * 4 + 0]);
    float f1 = warp_sum(hv0 * g_wa2r[lane * 4 + 1] + hv1 * g_wa2r[(lane + 32) * 4 + 1] +
                        fa0 * g_wa2r[(lane + 64) * 4 + 1] + fa1 * g_wa2r[(lane + 96) * 4 + 1]);
    float f2 = warp_sum(hv0 * g_wa2r[lane * 4 + 2] + hv1 * g_wa2r[(lane + 32) * 4 + 2] +
                        fa0 * g_wa2r[(lane + 64) * 4 + 2] + fa1 * g_wa2r[(lane + 96) * 4 + 2]);
    float f3 = warp_sum(hv0 * g_wa2r[lane * 4 + 3] + hv1 * g_wa2r[(lane + 32) * 4 + 3] +
                        fa0 * g_wa2r[(lane + 64) * 4 + 3] + fa1 * g_wa2r[(lane + 96) * 4 + 3]);
    float A0 = 0.f, A1 = 0.f, A2 = 0.f, A3 = 0.f;
    float e0 = 0.f, e1 = 0.f, e2 = 0.f, e3 = 0.f;
    for (int base = beg; base < end; base += 32) {
        int i = base + lane;
        int cnt = min(32, end - base);
        int s = 0; float p0 = 0.f, p1 = 0.f, p2 = 0.f, p3 = 0.f;
        if (i < end) {
            s = g_gt_srcs[i];
            float4 e = *(const float4*)(g_fsall + (size_t)s * 256 + 196);
            p0 = __expf(leaky(e.x + f0));
            p1 = __expf(leaky(e.y + f1));
            p2 = __expf(leaky(e.z + f2));
            p3 = __expf(leaky(e.w + f3));
            e0 += p0; e1 += p1; e2 += p2; e3 += p3;
        }
        for (int j = 0; j < cnt; j++) {
            int sj   = __shfl_sync(0xffffffffu, s, j);
            float q0 = __shfl_sync(0xffffffffu, p0, j);
            float q1 = __shfl_sync(0xffffffffu, p1, j);
            float q2 = __shfl_sync(0xffffffffu, p2, j);
            float q3 = __shfl_sync(0xffffffffu, p3, j);
            const float* fr = g_fsall + (size_t)sj * 256 + 64;
            A0 += fr[lane] * q0;
            A1 += fr[lane + 32] * q1;
            A2 += fr[lane + 64] * q2;
            A3 += fr[lane + 96] * q3;
        }
    }
    e0 = warp_sum(e0); e1 = warp_sum(e1); e2 = warp_sum(e2); e3 = warp_sum(e3);
    float r0 = e0 > 0.f ? A0 / e0 : 0.f;
    float r1 = e1 > 0.f ? A1 / e1 : 0.f;
    float r2 = e2 > 0.f ? A2 / e2 : 0.f;
    float r3 = e3 > 0.f ? A3 / e3 : 0.f;
    r0 = fmaxf(r0 + hv0 + b2[lane], 0.f);
    r1 = fmaxf(r1 + hv1 + b2[lane + 32], 0.f);
    r2 = fmaxf(r2 + fa0 + b2[lane + 64], 0.f);
    r3 = fmaxf(r3 + fa1 + b2[lane + 96], 0.f);
    g_h[n * 128 + lane] = r0;         g_xcat[n * 192 + lane] = r0;
    g_h[n * 128 + lane + 32] = r1;    g_xcat[n * 192 + lane + 32] = r1;
    g_h[n * 128 + lane + 64] = r2;    g_xcat[n * 192 + lane + 64] = r2;
    g_h[n * 128 + lane + 96] = r3;    g_xcat[n * 192 + lane + 96] = r3;
}

// ---------------- TF32 tensor-core GEMM (dense layers) ----------------
template <int BN, int RELU>
__global__ void __launch_bounds__(256)
k_mma(const float* __restrict__ A, const float* __restrict__ B,
      const float* __restrict__ bias, float* __restrict__ C,
      int M, int N, int K) {
    constexpr int WN  = BN / 64;
    constexpr int WM  = 8 / WN;
    constexpr int WTM = 128 / WM;
    constexpr int MT  = WTM / 16;
    constexpr int ALD = 36;
    constexpr int BLD = BN + 8;

    __shared__ uint32_t As[128 * ALD];
    __shared__ uint32_t Bs[32 * BLD];

    const int tid  = threadIdx.x;
    const int lane = tid & 31;
    const int warp = tid >> 5;
    const int g    = lane >> 2;
    const int t4   = lane & 3;
    const int wm   = warp / WN;
    const int wn   = warp % WN;
    const int wrow = wm * WTM;
    const int wcol = wn * 64;
    const int bm   = blockIdx.y * 128;
    const int bn   = blockIdx.x * BN;

    float acc[MT][8][4];
#pragma unroll
    for (int mt = 0; mt < MT; mt++)
#pragma unroll
        for (int nt = 0; nt < 8; nt++)
#pragma unroll
            for (int q = 0; q < 4; q++) acc[mt][nt][q] = 0.f;

    for (int k0 = 0; k0 < K; k0 += 32) {
#pragma unroll
        for (int it = 0; it < 4; it++) {
            int r = it * 32 + (tid >> 3);
            int c = (tid & 7) * 4;
            int gr = bm + r;
            float4 v = make_float4(0.f, 0.f, 0.f, 0.f);
            if (gr < M) v = *(const float4*)(A + (size_t)gr * K + k0 + c);
            uint4 u;
            u.x = f2tf32(v.x); u.y = f2tf32(v.y); u.z = f2tf32(v.z); u.w = f2tf32(v.w);
            *(uint4*)&As[r * ALD + c] = u;
        }
        if (BN == 128) {
#pragma unroll
            for (int it = 0; it < 4; it++) {
                int r = it * 8 + (tid >> 5);
                int c = (tid & 31) * 4;
                float4 v = *(const float4*)(B + (size_t)(k0 + r) * N + bn + c);
                uint4 u;
                u.x = f2tf32(v.x); u.y = f2tf32(v.y); u.z = f2tf32(v.z); u.w = f2tf32(v.w);
                *(uint4*)&Bs[r * BLD + c] = u;
            }
        } else {
#pragma unroll
            for (int it = 0; it < 2; it++) {
                int r = it * 16 + (tid >> 4);
                int c = (tid & 15) * 4;
                float4 v = *(const float4*)(B + (size_t)(k0 + r) * N + bn + c);
                uint4 u;
                u.x = f2tf32(v.x); u.y = f2tf32(v.y); u.z = f2tf32(v.z); u.w = f2tf32(v.w);
                *(uint4*)&Bs[r * BLD + c] = u;
            }
        }
        __syncthreads();

#pragma unroll
        for (int ks = 0; ks < 4; ks++) {
            int kk = ks * 8;
            uint32_t a[MT][4];
#pragma unroll
            for (int mt = 0; mt < MT; mt++) {
                int r = wrow + mt * 16;
                a[mt][0] = As[(r + g) * ALD + kk + t4];
                a[mt][1] = As[(r + g + 8) * ALD + kk + t4];
                a[mt][2] = As[(r + g) * ALD + kk + t4 + 4];
                a[mt][3] = As[(r + g + 8) * ALD + kk + t4 + 4];
            }
#pragma unroll
            for (int nt = 0; nt < 8; nt++) {
                int n0 = wcol + nt * 8;
                uint32_t b0 = Bs[(kk + t4) * BLD + n0 + g];
                uint32_t b1 = Bs[(kk + t4 + 4) * BLD + n0 + g];
#pragma unroll
                for (int mt = 0; mt < MT; mt++)
                    mma_tf32(acc[mt][nt], a[mt], b0, b1);
            }
        }
        __syncthreads();
    }

#pragma unroll
    for (int mt = 0; mt < MT; mt++) {
#pragma unroll
        for (int nt = 0; nt < 8; nt++) {
            int rr = bm + wrow + mt * 16 + g;
            int cc = bn + wcol + nt * 8 + 2 * t4;
            float bb0 = bias[cc], bb1 = bias[cc + 1];
            if (rr < M) {
                float v0 = acc[mt][nt][0] + bb0;
                float v1 = acc[mt][nt][1] + bb1;
                if (RELU) { v0 = fmaxf(v0, 0.f); v1 = fmaxf(v1, 0.f); }
                *(float2*)(C + (size_t)rr * N + cc) = make_float2(v0, v1);
            }
            if (rr + 8 < M) {
                float v0 = acc[mt][nt][2] + bb0;
                float v1 = acc[mt][nt][3] + bb1;
                if (RELU) { v0 = fmaxf(v0, 0.f); v1 = fmaxf(v1, 0.f); }
                *(float2*)(C + (size_t)(rr + 8) * N + cc) = make_float2(v0, v1);
            }
        }
    }
}

// ---------------- comm mailbox mean ----------------
__global__ void k_yagg() {
    int gid = blockIdx.x * blockDim.x + threadIdx.x;
    int n = gid >> 5;
    int lane = threadIdx.x & 31;
    if (n >= N_AG) return;
    int beg = g_cm_rowptr[n], end = g_cm_rowptr[n + 1];
    float a0 = 0.f, a1 = 0.f;
    int i = beg;
    for (; i + 1 < end; i += 2) {
        int s0 = g_cm_srcs[i], s1 = g_cm_srcs[i + 1];
        a0 += g_m[s0 * 64 + lane] + g_m[s1 * 64 + lane];
        a1 += g_m[s0 * 64 + lane + 32] + g_m[s1 * 64 + lane + 32];
    }
    if (i < end) {
        int s = g_cm_srcs[i];
        a0 += g_m[s * 64 + lane];
        a1 += g_m[s * 64 + lane + 32];
    }
    float inv = 1.f / fmaxf((float)(end - beg), 1.f);
    g_xcat[n * 192 + 128 + lane] = a0 * inv;
    g_xcat[n * 192 + 160 + lane] = a1 * inv;
}

// ---------------- GRU elementwise ----------------
__global__ void k_gru(const float* __restrict__ hprev) {
    int idx = blockIdx.x * blockDim.x + threadIdx.x;
    if (idx >= N_AG * 128) return;
    int n = idx >> 7, c = idx & 127;
    const float* gi = g_gi + n * 384;
    const float* gh = g_gh + n * 384;
    float r  = sigmoidf(gi[c] + gh[c]);
    float zg = sigmoidf(gi[128 + c] + gh[128 + c]);
    float ng = tanhf(gi[256 + c] + r * gh[256 + c]);
    float hp = hprev[n * 128 + c];
    float hv = (1.f - zg) * ng + zg * hp;
    g_h[idx] = hv;
    g_xcat[n * 192 + c] = hv;
}

// ---------------- output ----------------
__global__ void k_out(const float* __restrict__ ow, const float* __restrict__ ob,
                      float* __restrict__ out, int write_zz) {
    int gid = blockIdx.x * blockDim.x + threadIdx.x;
    int n = gid >> 5;
    int lane = threadIdx.x & 31;
    if (n >= N_AG) return;
    float p[5] = {0.f, 0.f, 0.f, 0.f, 0.f};
#pragma unroll
    for (int q = 0; q < 4; q++) {
        int d = lane + 32 * q;
        float hv = g_h[n * 128 + d];
        if (write_zz) out[N_AG * OUTD + n * 128 + d] = hv;
#pragma unroll
        for (int o = 0; o < 5; o++) p[o] += hv * ow[d * 5 + o];
    }
#pragma unroll
    for (int o = 0; o < 5; o++) p[o] = warp_sum(p[o]);
    if (lane == 0) {
#pragma unroll
        for (int o = 0; o < 5; o++) out[n * 5 + o] = p[o] + ob[o];
    }
}

// ---------------- launch ----------------
extern "C" void kernel_launch(void* const* d_in, const int* in_sizes, int n_in,
                              void* d_out, int out_size) {
    const float* feat_gt    = (const float*)d_in[0];
    const float* feat_agent = (const float*)d_in[1];
    const float* z          = (const float*)d_in[2];
    const int*   gt_src     = (const int*)d_in[3];
    const int*   gt_dst     = (const int*)d_in[4];
    const int*   cm_src     = (const int*)d_in[5];
    const int*   cm_dst     = (const int*)d_in[6];
    const float* w1_src     = (const float*)d_in[7];
    const float* w1_dst     = (const float*)d_in[8];
    const float* a1_l       = (const float*)d_in[9];
    const float* a1_r       = (const float*)d_in[10];
    const float* b1         = (const float*)d_in[11];
    const float* w2_src     = (const float*)d_in[12];
    const float* w2_dst     = (const float*)d_in[13];
    const float* a2_l       = (const float*)d_in[14];
    const float* a2_r       = (const float*)d_in[15];
    const float* b2         = (const float*)d_in[16];
    const float* enc_w1     = (const float*)d_in[17];
    const float* enc_b1     = (const float*)d_in[18];
    const float* enc_w2     = (const float*)d_in[19];
    const float* enc_b2     = (const float*)d_in[20];
    const float* gru_w_ih   = (const float*)d_in[21];
    const float* gru_w_hh   = (const float*)d_in[22];
    const float* gru_b_ih   = (const float*)d_in[23];
    const float* gru_b_hh   = (const float*)d_in[24];
    const float* out_w      = (const float*)d_in[25];
    const float* out_b      = (const float*)d_in[26];
    float* out = (float*)d_out;

    float *p_h, *p_hidden, *p_m, *p_xcat, *p_gi, *p_gh;
    cudaGetSymbolAddress((void**)&p_h, g_h);
    cudaGetSymbolAddress((void**)&p_hidden, g_hidden);
    cudaGetSymbolAddress((void**)&p_m, g_m);
    cudaGetSymbolAddress((void**)&p_xcat, g_xcat);
    cudaGetSymbolAddress((void**)&p_gi, g_gi);
    cudaGetSymbolAddress((void**)&p_gh, g_gh);

    int write_zz = (out_size >= N_AG * OUTD + N_AG * COMM) ? 1 : 0;

    // prep + CSR + src projection + merged GAT
    k_prep<<<1, 1024>>>(w1_src, w1_dst, a1_l, a1_r, w2_src, w2_dst, a2_l, a2_r);
    k_pack<<<32, 256>>>(w1_src, w2_src);
    k_zero<<<(N_AG + 1 + 255) / 256, 256>>>();
    k_hist<<<(E_GT + 255) / 256, 256>>>(gt_dst, cm_dst);
    k_scan<<<2, 1024>>>();
    k_scatter<<<(E_GT + 255) / 256, 256>>>(gt_src, gt_dst, cm_src, cm_dst);
    k_srcmma<<<dim3(4, (N_GT + 63) / 64), 256>>>(feat_gt);
    k_gat<<<(N_AG * 32 + 255) / 256, 256>>>(feat_agent, b1, b2);

    const int MB = (N_AG + 127) / 128;
    dim3 ge1(1, MB), ge2(1, MB), gg(3, MB);
    int gru_grid = (N_AG * 128 + 255) / 256;

    // comm step 0 (hprev = input z)
    k_mma<128, 1><<<ge1, 256>>>(p_h, enc_w1, enc_b1, p_hidden, N_AG, 128, 128);
    k_mma<64, 1><<<ge2, 256>>>(p_hidden, enc_w2, enc_b2, p_m, N_AG, 64, 128);
    k_yagg<<<(N_AG * 32 + 255) / 256, 256>>>();
    k_mma<128, 0><<<gg, 256>>>(p_xcat, gru_w_ih, gru_b_ih, p_gi, N_AG, 384, 192);
    k_mma<128, 0><<<gg, 256>>>(z, gru_w_hh, gru_b_hh, p_gh, N_AG, 384, 128);
    k_gru<<<gru_grid, 256>>>(z);

    // comm step 1 (hprev = h from step 0)
    k_mma<128, 1><<<ge1, 256>>>(p_h, enc_w1, enc_b1, p_hidden, N_AG, 128, 128);
    k_mma<64, 1><<<ge2, 256>>>(p_hidden, enc_w2, enc_b2, p_m, N_AG, 64, 128);
    k_yagg<<<(N_AG * 32 + 255) / 256, 256>>>();
    k_mma<128, 0><<<gg, 256>>>(p_xcat, gru_w_ih, gru_b_ih, p_gi, N_AG, 384, 192);
    k_mma<128, 0><<<gg, 256>>>(p_h, gru_w_hh, gru_b_hh, p_gh, N_AG, 384, 128);
    k_gru<<<gru_grid, 256>>>(p_h);

    k_out<<<(N_AG * 32 + 255) / 256, 256>>>(out_w, out_b, out, write_zz);
}